// round 1
// baseline (speedup 1.0000x reference)
#include <cuda_runtime.h>

// DiffJPEG forward: out = jpeg_compress(clip(x,0,1), quality=75)
// x, out: (16, 3, 512, 512) float32
//
// Fully fused: one CTA per 16x16 macroblock (4 Y blocks + 1 Cb + 1 Cr block).
// 384 threads: [0,256) handle luma, [256,384) handle chroma in lockstep phases.

#define IMG_H 512
#define IMG_W 512
#define BATCH 16

// DCT-II basis D[u][x] = 0.5*cos((2x+1)u*pi/16), row 0 scaled by 1/sqrt(2).
// Literals derived from float64 cos (matches reference table).
#define A1 0.4903926402016152f
#define A2 0.4619397662556434f
#define A3 0.4157348061512726f
#define A4 0.3535533905932738f
#define A5 0.2777851165098011f
#define A6 0.1913417161825449f
#define A7 0.0975451610080642f

__constant__ float c_D[8][8] = {
    { A4,  A4,  A4,  A4,  A4,  A4,  A4,  A4},
    { A1,  A3,  A5,  A7, -A7, -A5, -A3, -A1},
    { A2,  A6, -A6, -A2, -A2, -A6,  A6,  A2},
    { A3, -A7, -A1, -A5,  A5,  A1,  A7, -A3},
    { A4, -A4, -A4,  A4,  A4, -A4, -A4,  A4},
    { A5, -A1,  A7,  A3, -A3, -A7,  A1, -A5},
    { A6, -A2,  A2, -A6, -A6,  A2, -A2,  A6},
    { A7, -A5,  A3, -A1,  A1, -A3,  A5, -A7},
};

__constant__ float c_QY[8][8] = {
    {16, 11, 10, 16, 24, 40, 51, 61},
    {12, 12, 14, 19, 26, 58, 60, 55},
    {14, 13, 16, 24, 40, 57, 69, 56},
    {14, 17, 22, 29, 51, 87, 80, 62},
    {18, 22, 37, 56, 68, 109, 103, 77},
    {24, 35, 55, 64, 81, 104, 113, 92},
    {49, 64, 78, 87, 103, 121, 120, 101},
    {72, 92, 95, 98, 112, 100, 103, 99},
};

__constant__ float c_QC[8][8] = {
    {17, 18, 24, 47, 99, 99, 99, 99},
    {18, 21, 26, 66, 99, 99, 99, 99},
    {24, 26, 56, 99, 99, 99, 99, 99},
    {47, 66, 99, 99, 99, 99, 99, 99},
    {99, 99, 99, 99, 99, 99, 99, 99},
    {99, 99, 99, 99, 99, 99, 99, 99},
    {99, 99, 99, 99, 99, 99, 99, 99},
    {99, 99, 99, 99, 99, 99, 99, 99},
};

__global__ __launch_bounds__(384)
void diffjpeg_kernel(const float* __restrict__ x, float* __restrict__ out)
{
    __shared__ float sD[8][9];       // DCT basis (SMEM copy, conflict-free)
    __shared__ float sY[16][17];     // luma workspace (values, coefs, recon)
    __shared__ float tY[16][17];     // luma temp (stage intermediates)
    __shared__ float sCb[16][17];    // full-res Cb
    __shared__ float sCr[16][17];    // full-res Cr
    __shared__ float sC[2][8][9];    // downsampled chroma workspace
    __shared__ float tC[2][8][9];    // chroma temp

    const int tid = threadIdx.x;
    const int bx0 = blockIdx.x * 16;
    const int by0 = blockIdx.y * 16;
    const int b   = blockIdx.z;

    const size_t plane = (size_t)IMG_H * IMG_W;
    const size_t ibase = (size_t)b * 3 * plane;

    const int px = tid & 15;
    const int py = (tid >> 4) & 15;
    const size_t idx = ibase + (size_t)(by0 + py) * IMG_W + (bx0 + px);

    if (tid < 64) {
        sD[tid >> 3][tid & 7] = c_D[tid >> 3][tid & 7];
    }

    // ---- Load pixels, clip, scale, RGB -> YCbCr ----
    if (tid < 256) {
        float r  = x[idx];
        float g  = x[idx + plane];
        float bl = x[idx + 2 * plane];
        r  = fminf(fmaxf(r,  0.f), 1.f) * 255.f;
        g  = fminf(fmaxf(g,  0.f), 1.f) * 255.f;
        bl = fminf(fmaxf(bl, 0.f), 1.f) * 255.f;

        float Y  =  0.299f    * r + 0.587f    * g + 0.114f    * bl;
        float Cb = -0.168736f * r - 0.331264f * g + 0.5f      * bl + 128.f;
        float Cr =  0.5f      * r - 0.418688f * g - 0.081312f * bl + 128.f;

        sY[py][px]  = Y - 128.f;
        sCb[py][px] = Cb;
        sCr[py][px] = Cr;
    }
    __syncthreads();

    // ---- Phase A: luma fwd stage1 | chroma 2x2 downsample ----
    if (tid < 256) {
        const int blk = tid >> 6, e = tid & 63;
        const int u = e >> 3, v = e & 7;
        const int by = (blk >> 1) * 8, bx = (blk & 1) * 8;
        float s = 0.f;
#pragma unroll
        for (int k = 0; k < 8; k++) s += sD[u][k] * sY[by + k][bx + v];
        tY[by + u][bx + v] = s;
    } else {
        const int t = tid - 256, ch = t >> 6, e = t & 63;
        const int i = e >> 3, j = e & 7;
        float (*src)[17] = ch ? sCr : sCb;
        float avg = 0.25f * (src[2*i][2*j] + src[2*i][2*j+1] +
                             src[2*i+1][2*j] + src[2*i+1][2*j+1]);
        sC[ch][i][j] = avg - 128.f;
    }
    __syncthreads();

    // ---- Phase B: luma fwd stage2 + quantize | chroma fwd stage1 ----
    if (tid < 256) {
        const int blk = tid >> 6, e = tid & 63;
        const int u = e >> 3, v = e & 7;
        const int by = (blk >> 1) * 8, bx = (blk & 1) * 8;
        float s = 0.f;
#pragma unroll
        for (int k = 0; k < 8; k++) s += tY[by + u][bx + k] * sD[v][k];
        const float q = c_QY[u][v] * 0.5f;   // quality 75 -> factor 0.5
        sY[by + u][bx + v] = rintf(s / q) * q;
    } else {
        const int t = tid - 256, ch = t >> 6, e = t & 63;
        const int u = e >> 3, v = e & 7;
        float s = 0.f;
#pragma unroll
        for (int k = 0; k < 8; k++) s += sD[u][k] * sC[ch][k][v];
        tC[ch][u][v] = s;
    }
    __syncthreads();

    // ---- Phase C: luma inv stage1 | chroma fwd stage2 + quantize ----
    if (tid < 256) {
        const int blk = tid >> 6, e = tid & 63;
        const int xx = e >> 3, v = e & 7;
        const int by = (blk >> 1) * 8, bx = (blk & 1) * 8;
        float s = 0.f;
#pragma unroll
        for (int k = 0; k < 8; k++) s += sD[k][xx] * sY[by + k][bx + v];
        tY[by + xx][bx + v] = s;
    } else {
        const int t = tid - 256, ch = t >> 6, e = t & 63;
        const int u = e >> 3, v = e & 7;
        float s = 0.f;
#pragma unroll
        for (int k = 0; k < 8; k++) s += tC[ch][u][k] * sD[v][k];
        const float q = c_QC[u][v] * 0.5f;
        sC[ch][u][v] = rintf(s / q) * q;
    }
    __syncthreads();

    // ---- Phase D: luma inv stage2 (-> y_r) | chroma inv stage1 ----
    if (tid < 256) {
        const int blk = tid >> 6, e = tid & 63;
        const int xx = e >> 3, yy = e & 7;
        const int by = (blk >> 1) * 8, bx = (blk & 1) * 8;
        float s = 0.f;
#pragma unroll
        for (int k = 0; k < 8; k++) s += tY[by + xx][bx + k] * sD[k][yy];
        sY[by + xx][bx + yy] = s + 128.f;    // y_r
    } else {
        const int t = tid - 256, ch = t >> 6, e = t & 63;
        const int xx = e >> 3, v = e & 7;
        float s = 0.f;
#pragma unroll
        for (int k = 0; k < 8; k++) s += sD[k][xx] * sC[ch][k][v];
        tC[ch][xx][v] = s;
    }
    __syncthreads();

    // ---- Phase E: chroma inv stage2 (result is rec-128 = cbm/crm) ----
    if (tid >= 256) {
        const int t = tid - 256, ch = t >> 6, e = t & 63;
        const int xx = e >> 3, yy = e & 7;
        float s = 0.f;
#pragma unroll
        for (int k = 0; k < 8; k++) s += tC[ch][xx][k] * sD[k][yy];
        sC[ch][xx][yy] = s;                  // (rec+128)-128
    }
    __syncthreads();

    // ---- Phase F: upsample chroma, YCbCr -> RGB, clip, store ----
    if (tid < 256) {
        const float yv  = sY[py][px];
        const float cbm = sC[0][py >> 1][px >> 1];
        const float crm = sC[1][py >> 1][px >> 1];

        float r2 = yv + 1.402f * crm;
        float g2 = yv - 0.344136f * cbm - 0.714136f * crm;
        float b2 = yv + 1.772f * cbm;

        r2 = fminf(fmaxf(r2, 0.f), 255.f) / 255.f;
        g2 = fminf(fmaxf(g2, 0.f), 255.f) / 255.f;
        b2 = fminf(fmaxf(b2, 0.f), 255.f) / 255.f;

        out[idx]             = r2;
        out[idx + plane]     = g2;
        out[idx + 2 * plane] = b2;
    }
}

extern "C" void kernel_launch(void* const* d_in, const int* in_sizes, int n_in,
                              void* d_out, int out_size)
{
    const float* x = (const float*)d_in[0];
    float* out = (float*)d_out;
    dim3 grid(IMG_W / 16, IMG_H / 16, BATCH);
    diffjpeg_kernel<<<grid, 384>>>(x, out);
}

// round 3
// speedup vs baseline: 3.3209x; 3.3209x over previous
#include <cuda_runtime.h>

// DiffJPEG forward: out = jpeg_compress(clip(x,0,1), quality=75)
// x, out: (16, 3, 512, 512) float32
//
// One CTA per 32x16 pixel region: 8 Y blocks + 2 Cb + 2 Cr (12 blocks of 8x8).
// 96 threads, one thread per block-row. All matmuls in registers with the DCT
// basis folded to immediates; only the two 8x8 transposes touch SMEM.

#define IMG_H 512
#define IMG_W 512
#define BATCH 16

// DCT-II basis D[u][x] = 0.5*cos((2x+1)u*pi/16), row 0 scaled by 1/sqrt(2).
#define A1 0.4903926402016152f
#define A2 0.4619397662556434f
#define A3 0.4157348061512726f
#define A4 0.3535533905932738f
#define A5 0.2777851165098011f
#define A6 0.1913417161825449f
#define A7 0.0975451610080642f

// __device__ constexpr so fully-unrolled loops fold D entries into FFMA immediates
__device__ constexpr float Dm[8][8] = {
    { A4,  A4,  A4,  A4,  A4,  A4,  A4,  A4},
    { A1,  A3,  A5,  A7, -A7, -A5, -A3, -A1},
    { A2,  A6, -A6, -A2, -A2, -A6,  A6,  A2},
    { A3, -A7, -A1, -A5,  A5,  A1,  A7, -A3},
    { A4, -A4, -A4,  A4,  A4, -A4, -A4,  A4},
    { A5, -A1,  A7,  A3, -A3, -A7,  A1, -A5},
    { A6, -A2,  A2, -A6, -A6,  A2, -A2,  A6},
    { A7, -A5,  A3, -A1,  A1, -A3,  A5, -A7},
};

__constant__ float c_QY[8][8] = {
    {16, 11, 10, 16, 24, 40, 51, 61},
    {12, 12, 14, 19, 26, 58, 60, 55},
    {14, 13, 16, 24, 40, 57, 69, 56},
    {14, 17, 22, 29, 51, 87, 80, 62},
    {18, 22, 37, 56, 68, 109, 103, 77},
    {24, 35, 55, 64, 81, 104, 113, 92},
    {49, 64, 78, 87, 103, 121, 120, 101},
    {72, 92, 95, 98, 112, 100, 103, 99},
};

__constant__ float c_QC[8][8] = {
    {17, 18, 24, 47, 99, 99, 99, 99},
    {18, 21, 26, 66, 99, 99, 99, 99},
    {24, 26, 56, 99, 99, 99, 99, 99},
    {47, 66, 99, 99, 99, 99, 99, 99},
    {99, 99, 99, 99, 99, 99, 99, 99},
    {99, 99, 99, 99, 99, 99, 99, 99},
    {99, 99, 99, 99, 99, 99, 99, 99},
    {99, 99, 99, 99, 99, 99, 99, 99},
};

// Full fwd-DCT -> quantize -> inv-DCT for one 8x8 block row held in v[8].
// S: per-block 8x9 transpose scratch. Q: quant table (already * factor).
// r: this thread's row index within the block (0..7).
__device__ __forceinline__ void transform8(float v[8], float (*S)[9],
                                           const float (*Q)[9], int r)
{
    float t[8], m[8];

    // M1 = X * D^T   (thread holds row r of X)
#pragma unroll
    for (int j = 0; j < 8; j++) {
        float s = 0.f;
#pragma unroll
        for (int k = 0; k < 8; k++) s += v[k] * Dm[j][k];
        t[j] = s;
    }
    // transpose 1
#pragma unroll
    for (int j = 0; j < 8; j++) S[j][r] = t[j];
    __syncwarp();
#pragma unroll
    for (int j = 0; j < 8; j++) t[j] = S[r][j];
    __syncwarp();

    // M2 = M1^T * D^T  (= coef^T; thread holds column r of coef)
#pragma unroll
    for (int j = 0; j < 8; j++) {
        float s = 0.f;
#pragma unroll
        for (int k = 0; k < 8; k++) s += t[k] * Dm[j][k];
        m[j] = s;
    }
    // quantize: coef[j][r] -> q = Q[j][r]
#pragma unroll
    for (int j = 0; j < 8; j++) {
        float q = Q[j][r];
        m[j] = rintf(m[j] / q) * q;
    }
    // M3 = coef^T * D
#pragma unroll
    for (int j = 0; j < 8; j++) {
        float s = 0.f;
#pragma unroll
        for (int k = 0; k < 8; k++) s += m[k] * Dm[k][j];
        t[j] = s;
    }
    // transpose 2
#pragma unroll
    for (int j = 0; j < 8; j++) S[j][r] = t[j];
    __syncwarp();
#pragma unroll
    for (int j = 0; j < 8; j++) t[j] = S[r][j];
    __syncwarp();

    // M4 = M3^T * D = D^T * coef * D = rec  (thread holds row r)
#pragma unroll
    for (int j = 0; j < 8; j++) {
        float s = 0.f;
#pragma unroll
        for (int k = 0; k < 8; k++) s += t[k] * Dm[k][j];
        v[j] = s;
    }
}

__global__ __launch_bounds__(96)
void diffjpeg_kernel(const float* __restrict__ x, float* __restrict__ out)
{
    __shared__ float sP[2][16][20];     // horizontally-averaged chroma partials
    __shared__ float sS[12][8][9];      // per-block transpose scratch
    __shared__ float sQ[2][8][9];       // quant tables * factor
    __shared__ float sYrec[16][36];     // reconstructed luma (+128)
    __shared__ float sCrec[2][8][20];   // reconstructed chroma (centered)

    const int tid = threadIdx.x;
    const int bx0 = blockIdx.x * 32;
    const int by0 = blockIdx.y * 16;
    const size_t plane  = (size_t)IMG_H * IMG_W;
    const size_t ibase  = (size_t)blockIdx.z * 3 * plane;

    if (tid < 64) {
        int u = tid >> 3, v = tid & 7;
        sQ[0][u][v] = c_QY[u][v] * 0.5f;   // quality 75 -> factor 0.5
        sQ[1][u][v] = c_QC[u][v] * 0.5f;
    }

    if (tid < 64) {
        // ---- luma thread: block row ----
        const int blk  = tid >> 3, r = tid & 7;
        const int bcol = blk & 3,  brow = blk >> 2;
        const int lrow = brow * 8 + r;
        const int grow = by0 + lrow;
        const int gcol = bx0 + bcol * 8;

        const float4* pr = (const float4*)(x + ibase + (size_t)grow * IMG_W + gcol);
        const size_t p4 = plane / 4;
        float4 r0 = pr[0],        r1 = pr[1];
        float4 g0 = pr[p4],       g1 = pr[p4 + 1];
        float4 b0 = pr[2 * p4],   b1 = pr[2 * p4 + 1];

        float R[8] = {r0.x, r0.y, r0.z, r0.w, r1.x, r1.y, r1.z, r1.w};
        float G[8] = {g0.x, g0.y, g0.z, g0.w, g1.x, g1.y, g1.z, g1.w};
        float Bv[8]= {b0.x, b0.y, b0.z, b0.w, b1.x, b1.y, b1.z, b1.w};

        float y[8], cb[8], cr[8];
#pragma unroll
        for (int i = 0; i < 8; i++) {
            float rr = fminf(fmaxf(R[i],  0.f), 1.f) * 255.f;
            float gg = fminf(fmaxf(G[i],  0.f), 1.f) * 255.f;
            float bb = fminf(fmaxf(Bv[i], 0.f), 1.f) * 255.f;
            y[i]  =  0.299f    * rr + 0.587f    * gg + 0.114f    * bb - 128.f;
            cb[i] = -0.168736f * rr - 0.331264f * gg + 0.5f      * bb + 128.f;
            cr[i] =  0.5f      * rr - 0.418688f * gg - 0.081312f * bb + 128.f;
        }
        // horizontal pair averages -> partials
        float4 cbh = make_float4(0.5f * (cb[0] + cb[1]), 0.5f * (cb[2] + cb[3]),
                                 0.5f * (cb[4] + cb[5]), 0.5f * (cb[6] + cb[7]));
        float4 crh = make_float4(0.5f * (cr[0] + cr[1]), 0.5f * (cr[2] + cr[3]),
                                 0.5f * (cr[4] + cr[5]), 0.5f * (cr[6] + cr[7]));
        *(float4*)&sP[0][lrow][bcol * 4] = cbh;
        *(float4*)&sP[1][lrow][bcol * 4] = crh;
        __syncthreads();

        transform8(y, sS[blk], sQ[0], r);

        float4 o0 = make_float4(y[0] + 128.f, y[1] + 128.f, y[2] + 128.f, y[3] + 128.f);
        float4 o1 = make_float4(y[4] + 128.f, y[5] + 128.f, y[6] + 128.f, y[7] + 128.f);
        *(float4*)&sYrec[lrow][bcol * 8]     = o0;
        *(float4*)&sYrec[lrow][bcol * 8 + 4] = o1;
    } else {
        // ---- chroma thread: block row ----
        const int t  = tid - 64;
        const int ch = t >> 4;          // 0=Cb 1=Cr
        const int s2 = t & 15;
        const int bc = s2 >> 3, r = s2 & 7;

        __syncthreads();                // wait for partials

        float4 a0 = *(const float4*)&sP[ch][2 * r][bc * 8];
        float4 a1 = *(const float4*)&sP[ch][2 * r][bc * 8 + 4];
        float4 b0 = *(const float4*)&sP[ch][2 * r + 1][bc * 8];
        float4 b1 = *(const float4*)&sP[ch][2 * r + 1][bc * 8 + 4];

        float c[8];
        c[0] = 0.5f * (a0.x + b0.x) - 128.f;
        c[1] = 0.5f * (a0.y + b0.y) - 128.f;
        c[2] = 0.5f * (a0.z + b0.z) - 128.f;
        c[3] = 0.5f * (a0.w + b0.w) - 128.f;
        c[4] = 0.5f * (a1.x + b1.x) - 128.f;
        c[5] = 0.5f * (a1.y + b1.y) - 128.f;
        c[6] = 0.5f * (a1.z + b1.z) - 128.f;
        c[7] = 0.5f * (a1.w + b1.w) - 128.f;

        transform8(c, sS[8 + ch * 2 + bc], sQ[1], r);

        float4 o0 = make_float4(c[0], c[1], c[2], c[3]);
        float4 o1 = make_float4(c[4], c[5], c[6], c[7]);
        *(float4*)&sCrec[ch][r][bc * 8]     = o0;
        *(float4*)&sCrec[ch][r][bc * 8 + 4] = o1;
    }
    __syncthreads();

    // ---- output: upsample chroma, YCbCr -> RGB, clip, store ----
    const size_t obase = ibase + (size_t)by0 * IMG_W + bx0;
#pragma unroll
    for (int f = tid; f < 128; f += 96) {
        int row = f >> 3, c4 = f & 7;
        float4 yv = *(const float4*)&sYrec[row][c4 * 4];
        int crow = row >> 1, cc = c4 * 2;
        float cb0 = sCrec[0][crow][cc], cb1 = sCrec[0][crow][cc + 1];
        float cr0 = sCrec[1][crow][cc], cr1 = sCrec[1][crow][cc + 1];

        float yy[4] = {yv.x, yv.y, yv.z, yv.w};
        float cbm[4] = {cb0, cb0, cb1, cb1};
        float crm[4] = {cr0, cr0, cr1, cr1};

        float4 Ro, Go, Bo;
        float* Rp = &Ro.x; float* Gp = &Go.x; float* Bp = &Bo.x;
#pragma unroll
        for (int i = 0; i < 4; i++) {
            float r2 = yy[i] + 1.402f * crm[i];
            float g2 = yy[i] - 0.344136f * cbm[i] - 0.714136f * crm[i];
            float b2 = yy[i] + 1.772f * cbm[i];
            Rp[i] = fminf(fmaxf(r2, 0.f), 255.f) * (1.f / 255.f);
            Gp[i] = fminf(fmaxf(g2, 0.f), 255.f) * (1.f / 255.f);
            Bp[i] = fminf(fmaxf(b2, 0.f), 255.f) * (1.f / 255.f);
        }
        size_t o = obase + (size_t)row * IMG_W + c4 * 4;
        *(float4*)(out + o)             = Ro;
        *(float4*)(out + o + plane)     = Go;
        *(float4*)(out + o + 2 * plane) = Bo;
    }
}

extern "C" void kernel_launch(void* const* d_in, const int* in_sizes, int n_in,
                              void* d_out, int out_size)
{
    const float* x = (const float*)d_in[0];
    float* out = (float*)d_out;
    dim3 grid(IMG_W / 32, IMG_H / 16, BATCH);
    diffjpeg_kernel<<<grid, 96>>>(x, out);
}